// round 4
// baseline (speedup 1.0000x reference)
#include <cuda_runtime.h>

#define NN 50000
#define NE 800000

// ---- Scratch (__device__ globals; no allocation allowed) ----
__device__ float g_hp[NN * 128];     // relu(fc_pool(h))
__device__ float g_neigh[NN * 128];  // segment-max result
__device__ float g_h1[NN * 128];     // layer-1 output (first NN*64 used)
__device__ float g_h2[NN * 128];     // layer-2 output
__device__ int   g_deg[NN];          // in-degree histogram
__device__ int   g_off[NN + 1];      // CSR offsets (exclusive scan)
__device__ int   g_cur[NN];          // scatter cursors
__device__ int   g_esrc[NE];         // src sorted by dst
__device__ float g_eew[NE];          // edge weight sorted by dst

// Device-side buffer selection (avoids cudaGetSymbolAddress in capture region).
// sel: 0 -> g_h1, 1 -> g_h2, 2 -> external pointer (d_out / feat).
__device__ __forceinline__ float* buf_sel(int sel, float* ext) {
    return sel == 0 ? g_h1 : (sel == 1 ? g_h2 : ext);
}
__device__ __forceinline__ const float* cbuf_sel(int sel, const float* ext) {
    return sel == 0 ? g_h1 : (sel == 1 ? g_h2 : ext);
}

// ---- packed f32x2 helpers (SASS FFMA2; PTX-only pattern on sm_103a) ----
__device__ __forceinline__ unsigned long long dup2(float w) {
    unsigned long long r;
    asm("mov.b64 %0, {%1, %1};" : "=l"(r) : "f"(w));
    return r;
}
__device__ __forceinline__ void ffma2(unsigned long long& acc,
                                      unsigned long long a,
                                      unsigned long long b) {
    asm("fma.rn.f32x2 %0, %1, %2, %0;" : "+l"(acc) : "l"(a), "l"(b));
}
__device__ __forceinline__ float2 unpack2(unsigned long long v) {
    float lo, hi;
    asm("mov.b64 {%0, %1}, %2;" : "=f"(lo), "=f"(hi) : "l"(v));
    return make_float2(lo, hi);
}

// ===========================================================================
// CSR construction (once per launch; reused by all 3 layers)
// ===========================================================================
__global__ void zero_counters_kernel() {
    int i = blockIdx.x * blockDim.x + threadIdx.x;
    if (i < NN) { g_deg[i] = 0; g_cur[i] = 0; }
}

__global__ void histogram_kernel(const int* __restrict__ dst) {
    int e = blockIdx.x * blockDim.x + threadIdx.x;
    if (e < NE) atomicAdd(&g_deg[dst[e]], 1);
}

// Chunked exclusive scan: 1024 threads, each owns a contiguous chunk.
// Serial chunk sum -> one block scan of partials -> serial write-back.
__global__ void scan_kernel() {
    const int T = 1024;
    const int CH = (NN + T - 1) / T;  // 49
    __shared__ int s[T];
    int tid = threadIdx.x;
    int lo = tid * CH;
    int hi = min(lo + CH, NN);
    int sum = 0;
    for (int i = lo; i < hi; i++) sum += g_deg[i];
    s[tid] = sum;
    __syncthreads();
#pragma unroll
    for (int off = 1; off < T; off <<= 1) {
        int t = (tid >= off) ? s[tid - off] : 0;
        __syncthreads();
        s[tid] += t;
        __syncthreads();
    }
    int run = s[tid] - sum;  // exclusive prefix of this chunk
    for (int i = lo; i < hi; i++) {
        g_off[i] = run;
        run += g_deg[i];
    }
    if (tid == T - 1) g_off[NN] = run;
}

__global__ void scatter_edges_kernel(const int* __restrict__ src,
                                     const int* __restrict__ dst,
                                     const float* __restrict__ ew) {
    int e = blockIdx.x * blockDim.x + threadIdx.x;
    if (e < NE) {
        int d = dst[e];
        int p = g_off[d] + atomicAdd(&g_cur[d], 1);
        g_esrc[p] = src[e];
        g_eew[p] = ew[e];
    }
}

// ===========================================================================
// fc_pool: hp[row, j] = relu(sum_k h[row,k]*Wp[k,j] + bp[j]).
// Block computes R=8 rows x D cols. Inputs pair-interleaved in smem so one
// LDS.128 yields two k-steps of a packed row pair (f32x2 operands, no packs).
// ===========================================================================
template <int D>
__global__ void fc_pool_kernel(int hsel, const float* __restrict__ hext,
                               const float* __restrict__ Wp,
                               const float* __restrict__ bp) {
    constexpr int R = 8, P = R / 2;
    __shared__ __align__(16) float sp[P * D * 2];
    const float* __restrict__ h = cbuf_sel(hsel, hext);
    const int row0 = blockIdx.x * R;
    for (int idx = threadIdx.x; idx < R * D; idx += blockDim.x) {
        int r = idx / D, k = idx % D;
        sp[((r >> 1) * D + k) * 2 + (r & 1)] = h[(row0 + r) * D + k];
    }
    __syncthreads();
    const int j = threadIdx.x;
    unsigned long long acc[P];
    {
        unsigned long long b2 = dup2(bp[j]);
#pragma unroll
        for (int p = 0; p < P; p++) acc[p] = b2;
    }
#pragma unroll 4
    for (int k = 0; k < D; k += 2) {
        unsigned long long w0 = dup2(Wp[k * D + j]);
        unsigned long long w1 = dup2(Wp[(k + 1) * D + j]);
#pragma unroll
        for (int p = 0; p < P; p++) {
            ulonglong2 v = *reinterpret_cast<const ulonglong2*>(&sp[(p * D + k) * 2]);
            ffma2(acc[p], v.x, w0);
            ffma2(acc[p], v.y, w1);
        }
    }
#pragma unroll
    for (int p = 0; p < P; p++) {
        float2 f = unpack2(acc[p]);
        g_hp[(row0 + 2 * p + 0) * D + j] = fmaxf(f.x, 0.0f);
        g_hp[(row0 + 2 * p + 1) * D + j] = fmaxf(f.y, 0.0f);
    }
}

// ===========================================================================
// Per-node segment max over CSR in-edges. One thread = 4 columns (float4),
// D/4 threads per node. Empty segment -> 0 (messages >= 0; isfinite->0 rule).
// ===========================================================================
template <int D>
__global__ void segment_max_kernel() {
    constexpr int TPN = D / 4;                 // threads per node
    constexpr int NPB = 128 / TPN;             // nodes per block
    const int node = blockIdx.x * NPB + threadIdx.x / TPN;
    const int lane = threadIdx.x % TPN;
    if (node >= NN) return;
    const float4* __restrict__ hp4 = reinterpret_cast<const float4*>(g_hp);
    int i = g_off[node];
    const int end = g_off[node + 1];
    float4 m = make_float4(0.f, 0.f, 0.f, 0.f);
    for (; i + 3 < end; i += 4) {
        int s0 = g_esrc[i], s1 = g_esrc[i + 1], s2 = g_esrc[i + 2], s3 = g_esrc[i + 3];
        float w0 = g_eew[i], w1 = g_eew[i + 1], w2 = g_eew[i + 2], w3 = g_eew[i + 3];
        float4 v0 = hp4[s0 * TPN + lane];
        float4 v1 = hp4[s1 * TPN + lane];
        float4 v2 = hp4[s2 * TPN + lane];
        float4 v3 = hp4[s3 * TPN + lane];
        m.x = fmaxf(fmaxf(m.x, v0.x * w0), fmaxf(fmaxf(v1.x * w1, v2.x * w2), v3.x * w3));
        m.y = fmaxf(fmaxf(m.y, v0.y * w0), fmaxf(fmaxf(v1.y * w1, v2.y * w2), v3.y * w3));
        m.z = fmaxf(fmaxf(m.z, v0.z * w0), fmaxf(fmaxf(v1.z * w1, v2.z * w2), v3.z * w3));
        m.w = fmaxf(fmaxf(m.w, v0.w * w0), fmaxf(fmaxf(v1.w * w1, v2.w * w2), v3.w * w3));
    }
    for (; i < end; i++) {
        int s = g_esrc[i];
        float w = g_eew[i];
        float4 v = hp4[s * TPN + lane];
        m.x = fmaxf(m.x, v.x * w);
        m.y = fmaxf(m.y, v.y * w);
        m.z = fmaxf(m.z, v.z * w);
        m.w = fmaxf(m.w, v.w * w);
    }
    reinterpret_cast<float4*>(g_neigh)[node * TPN + lane] = m;
}

// ===========================================================================
// fc_out: out[row,j] = relu(sum_k h[row,k]*Ws[k,j] + neigh[row,k]*Wn[k,j] + b[j])
// Same pair-interleaved f32x2 scheme, two input matrices.
// ===========================================================================
template <int DIN, int DOUT>
__global__ void fc_out_kernel(int hsel, const float* __restrict__ hext,
                              const float* __restrict__ Ws,
                              const float* __restrict__ Wn,
                              const float* __restrict__ b,
                              int osel, float* __restrict__ oext) {
    constexpr int R = 8, P = R / 2;
    __shared__ __align__(16) float sph[P * DIN * 2];
    __shared__ __align__(16) float spn[P * DIN * 2];
    const float* __restrict__ h = cbuf_sel(hsel, hext);
    float* __restrict__ out = buf_sel(osel, oext);
    const int row0 = blockIdx.x * R;
    for (int idx = threadIdx.x; idx < R * DIN; idx += blockDim.x) {
        int r = idx / DIN, k = idx % DIN;
        int a = ((r >> 1) * DIN + k) * 2 + (r & 1);
        sph[a] = h[(row0 + r) * DIN + k];
        spn[a] = g_neigh[(row0 + r) * DIN + k];
    }
    __syncthreads();
    const int j = threadIdx.x;
    unsigned long long acc[P];
    {
        unsigned long long b2 = dup2(b[j]);
#pragma unroll
        for (int p = 0; p < P; p++) acc[p] = b2;
    }
#pragma unroll 2
    for (int k = 0; k < DIN; k += 2) {
        unsigned long long ws0 = dup2(Ws[k * DOUT + j]);
        unsigned long long ws1 = dup2(Ws[(k + 1) * DOUT + j]);
        unsigned long long wn0 = dup2(Wn[k * DOUT + j]);
        unsigned long long wn1 = dup2(Wn[(k + 1) * DOUT + j]);
#pragma unroll
        for (int p = 0; p < P; p++) {
            ulonglong2 vh = *reinterpret_cast<const ulonglong2*>(&sph[(p * DIN + k) * 2]);
            ulonglong2 vn = *reinterpret_cast<const ulonglong2*>(&spn[(p * DIN + k) * 2]);
            ffma2(acc[p], vh.x, ws0);
            ffma2(acc[p], vh.y, ws1);
            ffma2(acc[p], vn.x, wn0);
            ffma2(acc[p], vn.y, wn1);
        }
    }
#pragma unroll
    for (int p = 0; p < P; p++) {
        float2 f = unpack2(acc[p]);
        out[(row0 + 2 * p + 0) * DOUT + j] = fmaxf(f.x, 0.0f);
        out[(row0 + 2 * p + 1) * DOUT + j] = fmaxf(f.y, 0.0f);
    }
}

static inline int cdiv(long a, int b) { return (int)((a + b - 1) / b); }

extern "C" void kernel_launch(void* const* d_in, const int* in_sizes, int n_in,
                              void* d_out, int out_size) {
    const float* feat = (const float*)d_in[0];
    const int*   src  = (const int*)d_in[1];
    const int*   dst  = (const int*)d_in[2];
    const float* ew   = (const float*)d_in[3];

    const float* Wp1 = (const float*)d_in[4];
    const float* bp1 = (const float*)d_in[5];
    const float* Ws1 = (const float*)d_in[6];
    const float* Wn1 = (const float*)d_in[7];
    const float* b1  = (const float*)d_in[8];

    const float* Wp2 = (const float*)d_in[9];
    const float* bp2 = (const float*)d_in[10];
    const float* Ws2 = (const float*)d_in[11];
    const float* Wn2 = (const float*)d_in[12];
    const float* b2  = (const float*)d_in[13];

    const float* Wp3 = (const float*)d_in[14];
    const float* bp3 = (const float*)d_in[15];
    const float* Ws3 = (const float*)d_in[16];
    const float* Wn3 = (const float*)d_in[17];
    const float* b3  = (const float*)d_in[18];

    float* out = (float*)d_out;

    // ---- Build CSR (dst-sorted edges), reused by all layers ----
    zero_counters_kernel<<<cdiv(NN, 256), 256>>>();
    histogram_kernel<<<cdiv(NE, 256), 256>>>(dst);
    scan_kernel<<<1, 1024>>>();
    scatter_edges_kernel<<<cdiv(NE, 256), 256>>>(src, dst, ew);

    // ---------------- Layer 1: Din=128, Dout=64 (feat -> g_h1) ------------
    fc_pool_kernel<128><<<NN / 8, 128>>>(2, feat, Wp1, bp1);
    segment_max_kernel<128><<<NN / 4, 128>>>();
    fc_out_kernel<128, 64><<<NN / 8, 64>>>(2, feat, Ws1, Wn1, b1, 0, nullptr);

    // ---------------- Layer 2: Din=64, Dout=128 (g_h1 -> g_h2) ------------
    fc_pool_kernel<64><<<NN / 8, 64>>>(0, nullptr, Wp2, bp2);
    segment_max_kernel<64><<<NN / 8, 128>>>();
    fc_out_kernel<64, 128><<<NN / 8, 128>>>(0, nullptr, Ws2, Wn2, b2, 1, nullptr);

    // ---------------- Layer 3: Din=128, Dout=128 (g_h2 -> out) ------------
    fc_pool_kernel<128><<<NN / 8, 128>>>(1, nullptr, Wp3, bp3);
    segment_max_kernel<128><<<NN / 4, 128>>>();
    fc_out_kernel<128, 128><<<NN / 8, 128>>>(1, nullptr, Ws3, Wn3, b3, 2, out);
}